// round 1
// baseline (speedup 1.0000x reference)
#include <cuda_runtime.h>
#include <math.h>

#define BB 32
#define TT 512
#define CCH 512
#define HHD 512
#define G4 2048
#define MR (BB*TT)   // 16384

// ---------------- device scratch (static, allocation-free) ----------------
__device__ float d_scale[CCH];
__device__ float d_shift[CCH];
__device__ float d_Wfold[2][CCH*G4];      // 2 x 4 MB
__device__ float d_bfold[2][G4];
__device__ float d_G[2][MR*G4];           // 2 x 134 MB  (precomputed x@W' + b')
__device__ float d_hbuf[2][2][BB*HHD];    // [dir][pingpong][b*H]
__device__ float d_cbuf[2][BB*HHD];

#define STEP_SMEM (512*33*4 + 512*16*4)   // hs[512][33] + us[512][16] = 100352 B

// ---------------- BN fold prep ----------------
__global__ void bn_prep_kernel(const float* __restrict__ gamma,
                               const float* __restrict__ beta,
                               const float* __restrict__ mean,
                               const float* __restrict__ var) {
    int c = threadIdx.x;
    float s = gamma[c] * rsqrtf(var[c] + 1e-3f);
    d_scale[c] = s;
    d_shift[c] = beta[c] - mean[c] * s;
}

// W'[c][n] = W[c][n]*scale[c];  b'[n] = b[n] + sum_c shift[c]*W[c][n]
__global__ void fold_kernel(const float* __restrict__ Wf, const float* __restrict__ bf,
                            const float* __restrict__ Wb, const float* __restrict__ bb) {
    int gid = blockIdx.x * blockDim.x + threadIdx.x;   // 0..4095
    int dir = gid >> 11;
    int n = gid & 2047;
    const float* W = dir ? Wb : Wf;
    const float* bias = dir ? bb : bf;
    float* Wo = d_Wfold[dir];
    float acc = bias[n];
    for (int c = 0; c < CCH; c++) {
        float w = W[c * G4 + n];
        Wo[c * G4 + n] = w * d_scale[c];
        acc += d_shift[c] * w;
    }
    d_bfold[dir][n] = acc;
}

// ---------------- big GEMM: G = x @ W' + b'  (128x128x8, 8x8 micro) ----------------
__global__ __launch_bounds__(256) void gemm_kernel(const float* __restrict__ x) {
    const int BM = 128, BN = 128, BK = 8;
    int dir = blockIdx.z;
    const float* Wm = d_Wfold[dir];
    const float* bias = d_bfold[dir];
    float* Out = d_G[dir];

    __shared__ float As[BK][BM];   // transposed A tile
    __shared__ float Bs[BK][BN];

    int tid = threadIdx.x;
    int tr = tid / 16;            // 0..15
    int tc = tid % 16;            // 0..15
    int rowBase = blockIdx.y * BM;
    int colBase = blockIdx.x * BN;

    int aRow = tid >> 1;          // 0..127
    int aCol = (tid & 1) * 4;     // 0 or 4
    int bRow = tid >> 5;          // 0..7
    int bCol = (tid & 31) * 4;    // 0..124

    float acc[8][8] = {};

    for (int kt = 0; kt < CCH; kt += BK) {
        float4 av = *(const float4*)(x + (rowBase + aRow) * CCH + kt + aCol);
        As[aCol + 0][aRow] = av.x;
        As[aCol + 1][aRow] = av.y;
        As[aCol + 2][aRow] = av.z;
        As[aCol + 3][aRow] = av.w;
        *(float4*)&Bs[bRow][bCol] =
            *(const float4*)(Wm + (kt + bRow) * G4 + colBase + bCol);
        __syncthreads();

        #pragma unroll
        for (int k = 0; k < BK; k++) {
            float4 a0 = *(float4*)&As[k][tr * 8];
            float4 a1 = *(float4*)&As[k][tr * 8 + 4];
            float4 b0 = *(float4*)&Bs[k][tc * 8];
            float4 b1 = *(float4*)&Bs[k][tc * 8 + 4];
            float a[8] = {a0.x, a0.y, a0.z, a0.w, a1.x, a1.y, a1.z, a1.w};
            float b[8] = {b0.x, b0.y, b0.z, b0.w, b1.x, b1.y, b1.z, b1.w};
            #pragma unroll
            for (int i = 0; i < 8; i++)
                #pragma unroll
                for (int j = 0; j < 8; j++)
                    acc[i][j] = fmaf(a[i], b[j], acc[i][j]);
        }
        __syncthreads();
    }

    #pragma unroll
    for (int i = 0; i < 8; i++) {
        int row = rowBase + tr * 8 + i;
        #pragma unroll
        for (int j4 = 0; j4 < 8; j4 += 4) {
            int col = colBase + tc * 8 + j4;
            float4 v;
            v.x = acc[i][j4 + 0] + bias[col + 0];
            v.y = acc[i][j4 + 1] + bias[col + 1];
            v.z = acc[i][j4 + 2] + bias[col + 2];
            v.w = acc[i][j4 + 3] + bias[col + 3];
            *(float4*)(Out + row * G4 + col) = v;
        }
    }
}

// ---------------- state init ----------------
__global__ void init_kernel() {
    int i = blockIdx.x * blockDim.x + threadIdx.x;
    if (i < BB * HHD) {
        d_hbuf[0][0][i] = 0.f;
        d_hbuf[1][0][i] = 0.f;
        d_cbuf[0][i] = 0.f;
        d_cbuf[1][i] = 0.f;
    }
}

// ---------------- one recurrence step (both directions in one launch) ----------------
// grid (128, 2): blockIdx.x -> 4 hidden units (x4 gates = 16 U cols), blockIdx.y = dir
__global__ __launch_bounds__(256, 2) void step_kernel(const float* __restrict__ Uf,
                                                      const float* __restrict__ Ub,
                                                      int t) {
    extern __shared__ float smem[];
    float* hs = smem;                 // [512][33]  h transposed (hs[k][b])
    float* us = smem + 512 * 33;      // [512][16]  gathered U cols; reused as red[512][9]

    int dir = blockIdx.y;
    int unit0 = blockIdx.x * 4;
    int tid = threadIdx.x;
    int tt = dir ? (TT - 1 - t) : t;
    int rbuf = t & 1;
    const float* hg = d_hbuf[dir][rbuf];
    const float* U = dir ? Ub : Uf;

    // early loads for epilogue (independent of main loop)
    float gz[4] = {0.f, 0.f, 0.f, 0.f};
    float cold = 0.f;
    if (tid < 128) {
        int b = tid >> 2;
        int u = tid & 3;
        int rowoff = (b * TT + tt) * G4 + unit0 + u;
        const float* Gp = d_G[dir];
        gz[0] = Gp[rowoff];
        gz[1] = Gp[rowoff + 512];
        gz[2] = Gp[rowoff + 1024];
        gz[3] = Gp[rowoff + 1536];
        cold = d_cbuf[dir][b * HHD + unit0 + u];
    }

    // stage h transposed: hs[k][b] = h[b][k]
    for (int idx = tid; idx < (BB * HHD) / 4; idx += 256) {
        int b = idx >> 7;             // 128 float4s per batch row
        int k4 = (idx & 127) * 4;
        float4 v = *(const float4*)(hg + b * HHD + k4);
        hs[(k4 + 0) * 33 + b] = v.x;
        hs[(k4 + 1) * 33 + b] = v.y;
        hs[(k4 + 2) * 33 + b] = v.z;
        hs[(k4 + 3) * 33 + b] = v.w;
    }
    // stage gathered U columns: us[k][jj], jj = gate*4 + u
    for (int i = tid; i < 512 * 16; i += 256) {
        int k = i >> 4;
        int jj = i & 15;
        us[i] = U[k * G4 + (jj >> 2) * 512 + unit0 + (jj & 3)];
    }
    __syncthreads();

    // main GEMM: z[32][16] tile, K split across 8 warps
    int ks = tid >> 5;                // warp id = k-slice 0..7
    int p = tid & 31;
    int rgrp = p >> 2;                // 0..7
    int cgrp = p & 3;                 // 0..3
    float acc[4][4] = {};
    int k0 = ks * 64;
    #pragma unroll 4
    for (int k = k0; k < k0 + 64; k++) {
        float a0 = hs[k * 33 + rgrp];
        float a1 = hs[k * 33 + rgrp + 8];
        float a2 = hs[k * 33 + rgrp + 16];
        float a3 = hs[k * 33 + rgrp + 24];
        float4 bv = *(const float4*)&us[k * 16 + cgrp * 4];
        acc[0][0] = fmaf(a0, bv.x, acc[0][0]);
        acc[0][1] = fmaf(a0, bv.y, acc[0][1]);
        acc[0][2] = fmaf(a0, bv.z, acc[0][2]);
        acc[0][3] = fmaf(a0, bv.w, acc[0][3]);
        acc[1][0] = fmaf(a1, bv.x, acc[1][0]);
        acc[1][1] = fmaf(a1, bv.y, acc[1][1]);
        acc[1][2] = fmaf(a1, bv.z, acc[1][2]);
        acc[1][3] = fmaf(a1, bv.w, acc[1][3]);
        acc[2][0] = fmaf(a2, bv.x, acc[2][0]);
        acc[2][1] = fmaf(a2, bv.y, acc[2][1]);
        acc[2][2] = fmaf(a2, bv.z, acc[2][2]);
        acc[2][3] = fmaf(a2, bv.w, acc[2][3]);
        acc[3][0] = fmaf(a3, bv.x, acc[3][0]);
        acc[3][1] = fmaf(a3, bv.y, acc[3][1]);
        acc[3][2] = fmaf(a3, bv.z, acc[3][2]);
        acc[3][3] = fmaf(a3, bv.w, acc[3][3]);
    }
    __syncthreads();   // us no longer needed as U; reuse as reduction scratch

    float* red = us;   // [512 outputs][9 pad], uses 4608 floats <= 8192
    #pragma unroll
    for (int i = 0; i < 4; i++) {
        int r = rgrp + 8 * i;
        #pragma unroll
        for (int j = 0; j < 4; j++) {
            int c = cgrp * 4 + j;
            red[(r * 16 + c) * 9 + ks] = acc[i][j];
        }
    }
    __syncthreads();

    if (tid < 128) {
        int b = tid >> 2;
        int u = tid & 3;
        float z[4];
        #pragma unroll
        for (int gg = 0; gg < 4; gg++) {
            int o = b * 16 + gg * 4 + u;
            float s = gz[gg];
            #pragma unroll
            for (int kk = 0; kk < 8; kk++) s += red[o * 9 + kk];
            z[gg] = s;
        }
        float ig = 1.f / (1.f + expf(-z[0]));
        float fg = 1.f / (1.f + expf(-z[1]));
        float gv = tanhf(z[2]);
        float og = 1.f / (1.f + expf(-z[3]));
        float cn = fg * cold + ig * gv;
        int uidx = unit0 + u;
        d_cbuf[dir][b * HHD + uidx] = cn;
        d_hbuf[dir][1 - rbuf][b * HHD + uidx] = og * tanhf(cn);
    }
}

// ---------------- final concat ----------------
__global__ void final_kernel(float* __restrict__ out) {
    int i = blockIdx.x * blockDim.x + threadIdx.x;
    if (i < BB * 2 * HHD) {
        int b = i >> 10;
        int j = i & 1023;
        out[i] = (j < HHD) ? d_hbuf[0][0][b * HHD + j]
                           : d_hbuf[1][0][b * HHD + j - HHD];
    }
}

// ---------------- launch ----------------
extern "C" void kernel_launch(void* const* d_in, const int* in_sizes, int n_in,
                              void* d_out, int out_size) {
    const float* x     = (const float*)d_in[0];
    const float* gamma = (const float*)d_in[1];
    const float* beta  = (const float*)d_in[2];
    const float* mean  = (const float*)d_in[3];
    const float* var   = (const float*)d_in[4];
    const float* Wf    = (const float*)d_in[5];
    const float* Uf    = (const float*)d_in[6];
    const float* bf    = (const float*)d_in[7];
    const float* Wb    = (const float*)d_in[8];
    const float* Ub    = (const float*)d_in[9];
    const float* bb    = (const float*)d_in[10];
    float* out = (float*)d_out;

    cudaFuncSetAttribute(step_kernel, cudaFuncAttributeMaxDynamicSharedMemorySize,
                         STEP_SMEM);

    bn_prep_kernel<<<1, 512>>>(gamma, beta, mean, var);
    fold_kernel<<<16, 256>>>(Wf, bf, Wb, bb);

    dim3 ggrid(G4 / 128, MR / 128, 2);
    gemm_kernel<<<ggrid, 256>>>(x);

    init_kernel<<<64, 256>>>();

    dim3 sgrid(128, 2);
    for (int t = 0; t < TT; t++) {
        step_kernel<<<sgrid, 256, STEP_SMEM>>>(Uf, Ub, t);
    }

    final_kernel<<<128, 256>>>(out);
}

// round 2
// speedup vs baseline: 1.8444x; 1.8444x over previous
#include <cuda_runtime.h>
#include <math.h>

#define BB 32
#define TT 512
#define CCH 512
#define HHD 512
#define G4 2048
#define MR (BB*TT)   // 16384

#define UPB 8          // hidden units per persistent block
#define NBLK 128       // persistent grid (64 per direction)
#define HS_STRIDE 516  // padded stride for h in smem (conflict-free)

// smem: us[512][32] + hs[32][516] + redf[512*9*2]
#define LSTM_SMEM ((512*32 + 32*HS_STRIDE + 512*9*2) * 4)

// ---------------- device scratch ----------------
__device__ float d_scale[CCH];
__device__ float d_shift[CCH];
__device__ float d_G[2][(size_t)MR * G4];     // 2 x 134 MB
__device__ float d_hbuf[2][2][BB * HHD];      // [dir][pingpong]
__device__ volatile unsigned g_sense;
__device__ unsigned g_count;

// ---------------- f32x2 packed helpers ----------------
__device__ __forceinline__ unsigned long long pk2(float x, float y) {
    unsigned long long r;
    asm("mov.b64 %0, {%1, %2};" : "=l"(r) : "f"(x), "f"(y));
    return r;
}
__device__ __forceinline__ void upk2(unsigned long long v, float &x, float &y) {
    asm("mov.b64 {%0, %1}, %2;" : "=f"(x), "=f"(y) : "l"(v));
}
__device__ __forceinline__ void ffma2(unsigned long long &d,
                                      unsigned long long a, unsigned long long b) {
    asm("fma.rn.f32x2 %0, %1, %2, %0;" : "+l"(d) : "l"(a), "l"(b));
}

// ---------------- BN prep ----------------
__global__ void bn_prep_kernel(const float* __restrict__ gamma,
                               const float* __restrict__ beta,
                               const float* __restrict__ mean,
                               const float* __restrict__ var) {
    int c = threadIdx.x;
    float s = gamma[c] * rsqrtf(var[c] + 1e-3f);
    d_scale[c] = s;
    d_shift[c] = beta[c] - mean[c] * s;
}

// ---------------- big GEMM: G = BN(x) @ W + b  (128x128x8, f32x2) ----------------
__global__ __launch_bounds__(256, 2) void gemm_kernel(const float* __restrict__ x,
                                                      const float* __restrict__ Wf,
                                                      const float* __restrict__ bf,
                                                      const float* __restrict__ Wb,
                                                      const float* __restrict__ bb) {
    const int BM = 128, BN = 128, BK = 8;
    int dir = blockIdx.z;
    const float* Wm = dir ? Wb : Wf;
    const float* bias = dir ? bb : bf;
    float* Out = d_G[dir];

    __shared__ float As[BK][BM];   // BN folded into A at staging
    __shared__ float Bs[BK][BN];

    int tid = threadIdx.x;
    int tr = tid / 16;            // 0..15
    int tc = tid % 16;            // 0..15
    int rowBase = blockIdx.y * BM;
    int colBase = blockIdx.x * BN;

    int aRow = tid >> 1;          // 0..127
    int aCol = (tid & 1) * 4;     // 0 or 4
    int bRow = tid >> 5;          // 0..7
    int bCol = (tid & 31) * 4;    // 0..124

    unsigned long long acc[8][4]; // 8 rows x 4 col-pairs
    #pragma unroll
    for (int i = 0; i < 8; i++)
        #pragma unroll
        for (int j = 0; j < 4; j++) acc[i][j] = 0ull;

    for (int kt = 0; kt < CCH; kt += BK) {
        float4 av = *(const float4*)(x + (size_t)(rowBase + aRow) * CCH + kt + aCol);
        float4 sc = *(const float4*)(d_scale + kt + aCol);
        float4 sh = *(const float4*)(d_shift + kt + aCol);
        As[aCol + 0][aRow] = fmaf(av.x, sc.x, sh.x);
        As[aCol + 1][aRow] = fmaf(av.y, sc.y, sh.y);
        As[aCol + 2][aRow] = fmaf(av.z, sc.z, sh.z);
        As[aCol + 3][aRow] = fmaf(av.w, sc.w, sh.w);
        *(float4*)&Bs[bRow][bCol] =
            *(const float4*)(Wm + (size_t)(kt + bRow) * G4 + colBase + bCol);
        __syncthreads();

        #pragma unroll
        for (int k = 0; k < BK; k++) {
            float4 a0 = *(float4*)&As[k][tr * 8];
            float4 a1 = *(float4*)&As[k][tr * 8 + 4];
            ulonglong2 bA = *(ulonglong2*)&Bs[k][tc * 8];
            ulonglong2 bB = *(ulonglong2*)&Bs[k][tc * 8 + 4];
            unsigned long long ap[8];
            ap[0] = pk2(a0.x, a0.x); ap[1] = pk2(a0.y, a0.y);
            ap[2] = pk2(a0.z, a0.z); ap[3] = pk2(a0.w, a0.w);
            ap[4] = pk2(a1.x, a1.x); ap[5] = pk2(a1.y, a1.y);
            ap[6] = pk2(a1.z, a1.z); ap[7] = pk2(a1.w, a1.w);
            #pragma unroll
            for (int i = 0; i < 8; i++) {
                ffma2(acc[i][0], ap[i], bA.x);
                ffma2(acc[i][1], ap[i], bA.y);
                ffma2(acc[i][2], ap[i], bB.x);
                ffma2(acc[i][3], ap[i], bB.y);
            }
        }
        __syncthreads();
    }

    #pragma unroll
    for (int i = 0; i < 8; i++) {
        int row = rowBase + tr * 8 + i;
        float o[8];
        #pragma unroll
        for (int j = 0; j < 4; j++) upk2(acc[i][j], o[2 * j], o[2 * j + 1]);
        #pragma unroll
        for (int j4 = 0; j4 < 8; j4 += 4) {
            int col = colBase + tc * 8 + j4;
            float4 v;
            v.x = o[j4 + 0] + bias[col + 0];
            v.y = o[j4 + 1] + bias[col + 1];
            v.z = o[j4 + 2] + bias[col + 2];
            v.w = o[j4 + 3] + bias[col + 3];
            *(float4*)(Out + (size_t)row * G4 + col) = v;
        }
    }
}

// ---------------- state init ----------------
__global__ void init_kernel() {
    int i = blockIdx.x * blockDim.x + threadIdx.x;
    if (i < BB * HHD) {
        d_hbuf[0][0][i] = 0.f;
        d_hbuf[1][0][i] = 0.f;
    }
}

// ---------------- persistent bidirectional LSTM recurrence ----------------
// 128 blocks (<=148 SMs => all resident). Block = (dir, 8 hidden units).
// U columns cached in smem once; h via global ping-pong + soft grid barrier.
__global__ __launch_bounds__(256, 1) void lstm_persist(const float* __restrict__ Uf,
                                                       const float* __restrict__ Ub) {
    extern __shared__ float smem[];
    float* us   = smem;                       // [512][32]
    float* hs   = smem + 512 * 32;            // [32][HS_STRIDE]
    float* redf = hs + 32 * HS_STRIDE;        // [512 pair-outs][9 slices][2]

    int tid = threadIdx.x;
    int dir = blockIdx.x >> 6;
    int blk = blockIdx.x & 63;
    int u0 = blk * UPB;
    const float* U = dir ? Ub : Uf;
    const float* Gp = d_G[dir];

    // stage this block's 32 U columns once: us[k][gate*8+uu]
    for (int i = tid; i < 512 * 32; i += 256) {
        int k = i >> 5, j = i & 31;
        us[i] = U[(size_t)k * G4 + (j >> 3) * HHD + u0 + (j & 7)];
    }

    // compute-phase role
    int w = tid >> 5, lane = tid & 31;
    int rg = lane & 7;            // row group 0..7 (batch rows rg+8i)
    int cg = lane >> 3;           // col group 0..3 (cols cg*8..cg*8+7)
    int k0 = w * 64;
    // epilogue role: one (batch, unit) per thread
    int eb = tid >> 3, eu = tid & 7;

    float c = 0.f;
    unsigned sense_local = 0;
    __syncthreads();

    for (int t = 0; t < TT; t++) {
        int tt = dir ? (TT - 1 - t) : t;
        int rb = t & 1;
        const float* hg = d_hbuf[dir][rb];

        // prefetch this thread's 4 gate pre-activations from G
        float gz[4];
        {
            const float* gp = Gp + (size_t)(eb * TT + tt) * G4 + u0 + eu;
            gz[0] = __ldg(gp);
            gz[1] = __ldg(gp + 512);
            gz[2] = __ldg(gp + 1024);
            gz[3] = __ldg(gp + 1536);
        }

        // per-warp staging of this warp's k-slice of h (L2 reads, bypass L1)
        #pragma unroll
        for (int i = 0; i < 16; i++) {
            int idx = lane + 32 * i;           // 0..511
            int b = idx >> 4, q = idx & 15;
            float4 v = __ldcg((const float4*)(hg + b * HHD + k0 + q * 4));
            *(float4*)&hs[b * HS_STRIDE + k0 + q * 4] = v;
        }
        __syncwarp();

        // z-tile GEMM: 32 batches x 32 cols, K-slice per warp, f32x2
        unsigned long long acc[4][4];
        #pragma unroll
        for (int i = 0; i < 4; i++)
            #pragma unroll
            for (int j = 0; j < 4; j++) acc[i][j] = 0ull;

        #pragma unroll 4
        for (int k = k0; k < k0 + 64; k++) {
            float a0 = hs[(rg     ) * HS_STRIDE + k];
            float a1 = hs[(rg +  8) * HS_STRIDE + k];
            float a2 = hs[(rg + 16) * HS_STRIDE + k];
            float a3 = hs[(rg + 24) * HS_STRIDE + k];
            ulonglong2 bA = *(const ulonglong2*)&us[k * 32 + cg * 8];
            ulonglong2 bB = *(const ulonglong2*)&us[k * 32 + cg * 8 + 4];
            unsigned long long ap0 = pk2(a0, a0), ap1 = pk2(a1, a1);
            unsigned long long ap2 = pk2(a2, a2), ap3 = pk2(a3, a3);
            ffma2(acc[0][0], ap0, bA.x); ffma2(acc[0][1], ap0, bA.y);
            ffma2(acc[0][2], ap0, bB.x); ffma2(acc[0][3], ap0, bB.y);
            ffma2(acc[1][0], ap1, bA.x); ffma2(acc[1][1], ap1, bA.y);
            ffma2(acc[1][2], ap1, bB.x); ffma2(acc[1][3], ap1, bB.y);
            ffma2(acc[2][0], ap2, bA.x); ffma2(acc[2][1], ap2, bA.y);
            ffma2(acc[2][2], ap2, bB.x); ffma2(acc[2][3], ap2, bB.y);
            ffma2(acc[3][0], ap3, bA.x); ffma2(acc[3][1], ap3, bA.y);
            ffma2(acc[3][2], ap3, bB.x); ffma2(acc[3][3], ap3, bB.y);
        }

        // write per-slice partials: redf[(col2*32+row)*9 + w] as float2
        #pragma unroll
        for (int i = 0; i < 4; i++) {
            int row = rg + 8 * i;
            #pragma unroll
            for (int j = 0; j < 4; j++) {
                int col2 = cg * 4 + j;
                float xx, yy;
                upk2(acc[i][j], xx, yy);
                float2 v = make_float2(xx, yy);
                *(float2*)&redf[(((col2 << 5) | row) * 9 + w) * 2] = v;
            }
        }
        __syncthreads();

        // epilogue: reduce 8 slices, gates, state update
        {
            float z[4];
            #pragma unroll
            for (int g = 0; g < 4; g++) {
                int col = g * 8 + eu;
                int base = (((col >> 1) * 32 + eb) * 9) * 2 + (col & 1);
                float s = gz[g];
                #pragma unroll
                for (int sw = 0; sw < 8; sw++) s += redf[base + sw * 2];
                z[g] = s;
            }
            float ig = 1.f / (1.f + __expf(-z[0]));
            float fg = 1.f / (1.f + __expf(-z[1]));
            float gv = tanhf(z[2]);
            float og = 1.f / (1.f + __expf(-z[3]));
            c = fg * c + ig * gv;
            d_hbuf[dir][rb ^ 1][eb * HHD + u0 + eu] = og * tanhf(c);
        }

        // grid barrier (sense-reversing; 512 flips per launch -> replay-safe)
        __syncthreads();
        if (tid == 0) {
            sense_local ^= 1u;
            __threadfence();
            if (atomicAdd(&g_count, 1u) == NBLK - 1) {
                g_count = 0u;
                __threadfence();
                *(volatile unsigned*)&g_sense = sense_local;
            } else {
                while (*(volatile unsigned*)&g_sense != sense_local) { }
            }
            __threadfence();
        }
        __syncthreads();
    }
}

// ---------------- final concat ----------------
__global__ void final_kernel(float* __restrict__ out) {
    int i = blockIdx.x * blockDim.x + threadIdx.x;
    if (i < BB * 2 * HHD) {
        int b = i >> 10;
        int j = i & 1023;
        out[i] = (j < HHD) ? d_hbuf[0][0][b * HHD + j]
                           : d_hbuf[1][0][b * HHD + j - HHD];
    }
}

// ---------------- launch ----------------
extern "C" void kernel_launch(void* const* d_in, const int* in_sizes, int n_in,
                              void* d_out, int out_size) {
    const float* x     = (const float*)d_in[0];
    const float* gamma = (const float*)d_in[1];
    const float* beta  = (const float*)d_in[2];
    const float* mean  = (const float*)d_in[3];
    const float* var   = (const float*)d_in[4];
    const float* Wf    = (const float*)d_in[5];
    const float* Uf    = (const float*)d_in[6];
    const float* bf    = (const float*)d_in[7];
    const float* Wb    = (const float*)d_in[8];
    const float* Ub    = (const float*)d_in[9];
    const float* bb    = (const float*)d_in[10];
    float* out = (float*)d_out;

    cudaFuncSetAttribute(lstm_persist, cudaFuncAttributeMaxDynamicSharedMemorySize,
                         LSTM_SMEM);

    bn_prep_kernel<<<1, 512>>>(gamma, beta, mean, var);

    dim3 ggrid(G4 / 128, MR / 128, 2);
    gemm_kernel<<<ggrid, 256>>>(x, Wf, bf, Wb, bb);

    init_kernel<<<64, 256>>>();

    lstm_persist<<<NBLK, 256, LSTM_SMEM>>>(Uf, Ub);

    final_kernel<<<128, 256>>>(out);
}

// round 3
// speedup vs baseline: 1.9699x; 1.0680x over previous
#include <cuda_runtime.h>
#include <math.h>

#define BB 32
#define TT 512
#define CCH 512
#define HHD 512
#define G4 2048
#define MR (BB*TT)   // 16384

#define UPB 8          // hidden units per persistent block
#define NBLK 128       // persistent grid (64 per direction)
#define HS_STRIDE 516  // padded stride for h in smem

#define LSTM_SMEM ((512*32 + 32*HS_STRIDE + 512*9*2) * 4)

// ---------------- device scratch ----------------
__device__ float d_scale[CCH];
__device__ float d_shift[CCH];
__device__ float d_G[2][(size_t)MR * G4];     // 2 x 134 MB
__device__ float d_hbuf[2][2][BB * HHD];
__device__ volatile unsigned g_sense;
__device__ unsigned g_count;

// ---------------- f32x2 packed helpers (recurrence) ----------------
__device__ __forceinline__ unsigned long long pk2(float x, float y) {
    unsigned long long r;
    asm("mov.b64 %0, {%1, %2};" : "=l"(r) : "f"(x), "f"(y));
    return r;
}
__device__ __forceinline__ void upk2(unsigned long long v, float &x, float &y) {
    asm("mov.b64 {%0, %1}, %2;" : "=f"(x), "=f"(y) : "l"(v));
}
__device__ __forceinline__ void ffma2(unsigned long long &d,
                                      unsigned long long a, unsigned long long b) {
    asm("fma.rn.f32x2 %0, %1, %2, %0;" : "+l"(d) : "l"(a), "l"(b));
}

// ---------------- tf32 helpers ----------------
__device__ __forceinline__ unsigned f2tf32(float f) {
    unsigned r;
    asm("cvt.rna.tf32.f32 %0, %1;" : "=r"(r) : "f"(f));
    return r;
}
__device__ __forceinline__ void split_tf32(float f, unsigned &hi, unsigned &lo) {
    hi = f2tf32(f);
    float hif = __uint_as_float(hi);
    lo = f2tf32(f - hif);
}
__device__ __forceinline__ void mma_tf32(float* d, const unsigned* a, const unsigned* b) {
    asm("mma.sync.aligned.m16n8k8.row.col.f32.tf32.tf32.f32 "
        "{%0,%1,%2,%3}, {%4,%5,%6,%7}, {%8,%9}, {%0,%1,%2,%3};"
        : "+f"(d[0]), "+f"(d[1]), "+f"(d[2]), "+f"(d[3])
        : "r"(a[0]), "r"(a[1]), "r"(a[2]), "r"(a[3]), "r"(b[0]), "r"(b[1]));
}

// ---------------- BN prep ----------------
__global__ void bn_prep_kernel(const float* __restrict__ gamma,
                               const float* __restrict__ beta,
                               const float* __restrict__ mean,
                               const float* __restrict__ var) {
    int c = threadIdx.x;
    float s = gamma[c] * rsqrtf(var[c] + 1e-3f);
    d_scale[c] = s;
    d_shift[c] = beta[c] - mean[c] * s;
}

// ---------------- big GEMM: G = BN(x)@W + b via 3xTF32 mma.sync ----------------
// block 128x128, BK=16, 8 warps as 2(m) x 4(n), warp tile 64x32
#define SSTR 136   // smem row stride (floats): bank-bijective for frag loads

__global__ __launch_bounds__(256, 2) void gemm_tc_kernel(const float* __restrict__ x,
                                                         const float* __restrict__ Wf,
                                                         const float* __restrict__ bf,
                                                         const float* __restrict__ Wb,
                                                         const float* __restrict__ bb) {
    __shared__ float As[16 * SSTR];   // [k][m]
    __shared__ float Bs[16 * SSTR];   // [k][n]

    int dir = blockIdx.z;
    const float* Wm = dir ? Wb : Wf;
    const float* bias = dir ? bb : bf;
    float* Out = d_G[dir];

    int tid = threadIdx.x;
    int warp = tid >> 5, lane = tid & 31;
    int gid = lane >> 2, tig = lane & 3;
    int wm = warp >> 2, wn = warp & 3;          // 2 x 4 warps
    int rowBase = blockIdx.y * 128;
    int colBase = blockIdx.x * 128;

    // staging roles
    int aRow = tid >> 1;                 // 0..127
    int aK = (tid & 1) * 8;              // 0 or 8
    int bK = tid >> 4;                   // 0..15
    int bN = (tid & 15) * 8;             // 0..120

    float acc[4][4][4];                  // [mi][ni][frag]
    #pragma unroll
    for (int i = 0; i < 4; i++)
        #pragma unroll
        for (int j = 0; j < 4; j++)
            #pragma unroll
            for (int q = 0; q < 4; q++) acc[i][j][q] = 0.f;

    const float* xrow = x + (size_t)(rowBase + aRow) * CCH;
    for (int kt = 0; kt < CCH; kt += 16) {
        // stage A (BN folded), transposed to [k][m]
        {
            float4 v0 = *(const float4*)(xrow + kt + aK);
            float4 v1 = *(const float4*)(xrow + kt + aK + 4);
            float4 sc0 = *(const float4*)(d_scale + kt + aK);
            float4 sc1 = *(const float4*)(d_scale + kt + aK + 4);
            float4 sh0 = *(const float4*)(d_shift + kt + aK);
            float4 sh1 = *(const float4*)(d_shift + kt + aK + 4);
            As[(aK + 0) * SSTR + aRow] = fmaf(v0.x, sc0.x, sh0.x);
            As[(aK + 1) * SSTR + aRow] = fmaf(v0.y, sc0.y, sh0.y);
            As[(aK + 2) * SSTR + aRow] = fmaf(v0.z, sc0.z, sh0.z);
            As[(aK + 3) * SSTR + aRow] = fmaf(v0.w, sc0.w, sh0.w);
            As[(aK + 4) * SSTR + aRow] = fmaf(v1.x, sc1.x, sh1.x);
            As[(aK + 5) * SSTR + aRow] = fmaf(v1.y, sc1.y, sh1.y);
            As[(aK + 6) * SSTR + aRow] = fmaf(v1.z, sc1.z, sh1.z);
            As[(aK + 7) * SSTR + aRow] = fmaf(v1.w, sc1.w, sh1.w);
            const float* wp = Wm + (size_t)(kt + bK) * G4 + colBase + bN;
            *(float4*)&Bs[bK * SSTR + bN] = *(const float4*)wp;
            *(float4*)&Bs[bK * SSTR + bN + 4] = *(const float4*)(wp + 4);
        }
        __syncthreads();

        #pragma unroll
        for (int kf = 0; kf < 16; kf += 8) {
            // A fragments (hi/lo) for 4 m-tiles
            unsigned ah[4][4], al[4][4];
            #pragma unroll
            for (int mi = 0; mi < 4; mi++) {
                int m = wm * 64 + mi * 16 + gid;
                float f0 = As[(kf + tig) * SSTR + m];
                float f1 = As[(kf + tig) * SSTR + m + 8];
                float f2 = As[(kf + tig + 4) * SSTR + m];
                float f3 = As[(kf + tig + 4) * SSTR + m + 8];
                split_tf32(f0, ah[mi][0], al[mi][0]);
                split_tf32(f1, ah[mi][1], al[mi][1]);
                split_tf32(f2, ah[mi][2], al[mi][2]);
                split_tf32(f3, ah[mi][3], al[mi][3]);
            }
            #pragma unroll
            for (int ni = 0; ni < 4; ni++) {
                int n = wn * 32 + ni * 8 + gid;
                unsigned bh[2], bl[2];
                float g0 = Bs[(kf + tig) * SSTR + n];
                float g1 = Bs[(kf + tig + 4) * SSTR + n];
                split_tf32(g0, bh[0], bl[0]);
                split_tf32(g1, bh[1], bl[1]);
                #pragma unroll
                for (int mi = 0; mi < 4; mi++) {
                    mma_tf32(acc[mi][ni], ah[mi], bh);
                    mma_tf32(acc[mi][ni], ah[mi], bl);
                    mma_tf32(acc[mi][ni], al[mi], bh);
                }
            }
        }
        __syncthreads();
    }

    // epilogue: + bias, store
    #pragma unroll
    for (int mi = 0; mi < 4; mi++) {
        int row0 = rowBase + wm * 64 + mi * 16 + gid;
        #pragma unroll
        for (int ni = 0; ni < 4; ni++) {
            int col = colBase + wn * 32 + ni * 8 + tig * 2;
            float b0 = bias[col], b1 = bias[col + 1];
            float2 v0 = make_float2(acc[mi][ni][0] + b0, acc[mi][ni][1] + b1);
            float2 v1 = make_float2(acc[mi][ni][2] + b0, acc[mi][ni][3] + b1);
            *(float2*)(Out + (size_t)row0 * G4 + col) = v0;
            *(float2*)(Out + (size_t)(row0 + 8) * G4 + col) = v1;
        }
    }
}

// ---------------- state init ----------------
__global__ void init_kernel() {
    int i = blockIdx.x * blockDim.x + threadIdx.x;
    if (i < BB * HHD) {
        d_hbuf[0][0][i] = 0.f;
        d_hbuf[1][0][i] = 0.f;
    }
}

// ---------------- persistent bidirectional LSTM recurrence ----------------
__global__ __launch_bounds__(256, 1) void lstm_persist(const float* __restrict__ Uf,
                                                       const float* __restrict__ Ub) {
    extern __shared__ float smem[];
    float* us   = smem;                       // [512][32]
    float* hs   = smem + 512 * 32;            // [32][HS_STRIDE]
    float* redf = hs + 32 * HS_STRIDE;        // [512][9][2]

    int tid = threadIdx.x;
    int dir = blockIdx.x >> 6;
    int blk = blockIdx.x & 63;
    int u0 = blk * UPB;
    const float* U = dir ? Ub : Uf;
    const float* Gp = d_G[dir];

    for (int i = tid; i < 512 * 32; i += 256) {
        int k = i >> 5, j = i & 31;
        us[i] = U[(size_t)k * G4 + (j >> 3) * HHD + u0 + (j & 7)];
    }

    int w = tid >> 5, lane = tid & 31;
    int rg = lane & 7;
    int cg = lane >> 3;
    int k0 = w * 64;
    int eb = tid >> 3, eu = tid & 7;

    float c = 0.f;
    unsigned sense_local = 0;
    __syncthreads();

    for (int t = 0; t < TT; t++) {
        int tt = dir ? (TT - 1 - t) : t;
        int rb = t & 1;
        const float* hg = d_hbuf[dir][rb];

        float gz[4];
        {
            const float* gp = Gp + (size_t)(eb * TT + tt) * G4 + u0 + eu;
            gz[0] = __ldg(gp);
            gz[1] = __ldg(gp + 512);
            gz[2] = __ldg(gp + 1024);
            gz[3] = __ldg(gp + 1536);
        }

        #pragma unroll
        for (int i = 0; i < 16; i++) {
            int idx = lane + 32 * i;
            int b = idx >> 4, q = idx & 15;
            float4 v = __ldcg((const float4*)(hg + b * HHD + k0 + q * 4));
            *(float4*)&hs[b * HS_STRIDE + k0 + q * 4] = v;
        }
        __syncwarp();

        unsigned long long acc[4][4];
        #pragma unroll
        for (int i = 0; i < 4; i++)
            #pragma unroll
            for (int j = 0; j < 4; j++) acc[i][j] = 0ull;

        #pragma unroll 4
        for (int k = k0; k < k0 + 64; k++) {
            float a0 = hs[(rg     ) * HS_STRIDE + k];
            float a1 = hs[(rg +  8) * HS_STRIDE + k];
            float a2 = hs[(rg + 16) * HS_STRIDE + k];
            float a3 = hs[(rg + 24) * HS_STRIDE + k];
            ulonglong2 bA = *(const ulonglong2*)&us[k * 32 + cg * 8];
            ulonglong2 bB = *(const ulonglong2*)&us[k * 32 + cg * 8 + 4];
            unsigned long long ap0 = pk2(a0, a0), ap1 = pk2(a1, a1);
            unsigned long long ap2 = pk2(a2, a2), ap3 = pk2(a3, a3);
            ffma2(acc[0][0], ap0, bA.x); ffma2(acc[0][1], ap0, bA.y);
            ffma2(acc[0][2], ap0, bB.x); ffma2(acc[0][3], ap0, bB.y);
            ffma2(acc[1][0], ap1, bA.x); ffma2(acc[1][1], ap1, bA.y);
            ffma2(acc[1][2], ap1, bB.x); ffma2(acc[1][3], ap1, bB.y);
            ffma2(acc[2][0], ap2, bA.x); ffma2(acc[2][1], ap2, bA.y);
            ffma2(acc[2][2], ap2, bB.x); ffma2(acc[2][3], ap2, bB.y);
            ffma2(acc[3][0], ap3, bA.x); ffma2(acc[3][1], ap3, bA.y);
            ffma2(acc[3][2], ap3, bB.x); ffma2(acc[3][3], ap3, bB.y);
        }

        #pragma unroll
        for (int i = 0; i < 4; i++) {
            int row = rg + 8 * i;
            #pragma unroll
            for (int j = 0; j < 4; j++) {
                int col2 = cg * 4 + j;
                float xx, yy;
                upk2(acc[i][j], xx, yy);
                *(float2*)&redf[(((col2 << 5) | row) * 9 + w) * 2] = make_float2(xx, yy);
            }
        }
        __syncthreads();

        {
            float z[4];
            #pragma unroll
            for (int g = 0; g < 4; g++) {
                int col = g * 8 + eu;
                int base = (((col >> 1) * 32 + eb) * 9) * 2 + (col & 1);
                float s = gz[g];
                #pragma unroll
                for (int sw = 0; sw < 8; sw++) s += redf[base + sw * 2];
                z[g] = s;
            }
            float ig = 1.f / (1.f + __expf(-z[0]));
            float fg = 1.f / (1.f + __expf(-z[1]));
            float gv = tanhf(z[2]);
            float og = 1.f / (1.f + __expf(-z[3]));
            c = fg * c + ig * gv;
            d_hbuf[dir][rb ^ 1][eb * HHD + u0 + eu] = og * tanhf(c);
        }

        __syncthreads();
        if (tid == 0) {
            sense_local ^= 1u;
            __threadfence();
            if (atomicAdd(&g_count, 1u) == NBLK - 1) {
                g_count = 0u;
                __threadfence();
                *(volatile unsigned*)&g_sense = sense_local;
            } else {
                while (*(volatile unsigned*)&g_sense != sense_local) { }
            }
            __threadfence();
        }
        __syncthreads();
    }
}

// ---------------- final concat ----------------
__global__ void final_kernel(float* __restrict__ out) {
    int i = blockIdx.x * blockDim.x + threadIdx.x;
    if (i < BB * 2 * HHD) {
        int b = i >> 10;
        int j = i & 1023;
        out[i] = (j < HHD) ? d_hbuf[0][0][b * HHD + j]
                           : d_hbuf[1][0][b * HHD + j - HHD];
    }
}

// ---------------- launch ----------------
extern "C" void kernel_launch(void* const* d_in, const int* in_sizes, int n_in,
                              void* d_out, int out_size) {
    const float* x     = (const float*)d_in[0];
    const float* gamma = (const float*)d_in[1];
    const float* beta  = (const float*)d_in[2];
    const float* mean  = (const float*)d_in[3];
    const float* var   = (const float*)d_in[4];
    const float* Wf    = (const float*)d_in[5];
    const float* Uf    = (const float*)d_in[6];
    const float* bf    = (const float*)d_in[7];
    const float* Wb    = (const float*)d_in[8];
    const float* Ub    = (const float*)d_in[9];
    const float* bb    = (const float*)d_in[10];
    float* out = (float*)d_out;

    cudaFuncSetAttribute(lstm_persist, cudaFuncAttributeMaxDynamicSharedMemorySize,
                         LSTM_SMEM);

    bn_prep_kernel<<<1, 512>>>(gamma, beta, mean, var);

    dim3 ggrid(G4 / 128, MR / 128, 2);
    gemm_tc_kernel<<<ggrid, 256>>>(x, Wf, bf, Wb, bb);

    init_kernel<<<64, 256>>>();

    lstm_persist<<<NBLK, 256, LSTM_SMEM>>>(Uf, Ub);

    final_kernel<<<128, 256>>>(out);
}